// round 1
// baseline (speedup 1.0000x reference)
#include <cuda_runtime.h>
#include <cstdint>

// ---------------------------------------------------------------------------
// AggrEGATConv: fused EGAT convolution
//   inputs (metadata order):
//     0 nfeats [N,128] f32    1 efeats [E,64] f32
//     2 src [E] i32           3 dst [E] i32
//     4 W_ni [128,64] f32     5 W_nj [128,64] f32
//     6 W_fij [64,64] f32     7 W_src [128,64] f32
//     8 b_src [64] f32        9 attn [4,16] f32      10 bias_e [64] f32
//   output: res_n [N,16] followed by res_e [E,16], f32
// ---------------------------------------------------------------------------

#define MAXN 100000
#define MAXE 1600000

// device scratch (allocation-free rule: static __device__ arrays)
__device__ float g_fni [(size_t)MAXN * 64];
__device__ float g_fnj [(size_t)MAXN * 64];
__device__ float g_hsrc[(size_t)MAXN * 64];
__device__ float g_ex  [(size_t)MAXE * 4];
__device__ float g_z   [(size_t)MAXN * 4];

// ---- packed f32x2 helpers (Blackwell FFMA2) -------------------------------
__device__ __forceinline__ unsigned long long pack2(float x, float y) {
    unsigned long long r;
    asm("mov.b64 %0, {%1, %2};"
        : "=l"(r) : "r"(__float_as_uint(x)), "r"(__float_as_uint(y)));
    return r;
}
__device__ __forceinline__ unsigned long long ffma2(unsigned long long a,
                                                    unsigned long long b,
                                                    unsigned long long c) {
    unsigned long long d;
    asm("fma.rn.f32x2 %0, %1, %2, %3;" : "=l"(d) : "l"(a), "l"(b), "l"(c));
    return d;
}
__device__ __forceinline__ float2 unpack2(unsigned long long v) {
    unsigned lo, hi;
    asm("mov.b64 {%0, %1}, %2;" : "=r"(lo), "=r"(hi) : "l"(v));
    return make_float2(__uint_as_float(lo), __uint_as_float(hi));
}

// ---------------------------------------------------------------------------
// Kernel 0: zero res_n region of output and the softmax denominator z.
// ---------------------------------------------------------------------------
__global__ void zero_kernel(float* __restrict__ out_n, int N) {
    int i = blockIdx.x * 256 + threadIdx.x;
    if (i < N * 16) out_n[i] = 0.0f;
    if (i < N * 4)  g_z[i]   = 0.0f;
}

// ---------------------------------------------------------------------------
// Kernel 1: node GEMMs.  blockIdx.y selects {W_ni -> g_fni, W_nj -> g_fnj,
// W_src(+b_src) -> g_hsrc}.  One thread = one node = 64 outputs (32 f32x2).
// W (128x64 f32 = 32KB) staged in shared; all lanes broadcast-read it.
// ---------------------------------------------------------------------------
__global__ __launch_bounds__(128)
void node_gemm(const float* __restrict__ nf,
               const float* __restrict__ Wni,
               const float* __restrict__ Wnj,
               const float* __restrict__ Wsrc,
               const float* __restrict__ bsrc,
               int N)
{
    __shared__ float4 sW[128 * 16];   // 32 KB
    __shared__ float  sb[64];

    const int which = blockIdx.y;
    const float* W = (which == 0) ? Wni : (which == 1) ? Wnj : Wsrc;
    float* out = (which == 0) ? g_fni : (which == 1) ? g_fnj : g_hsrc;

    const float4* Wv = (const float4*)W;
    for (int i = threadIdx.x; i < 2048; i += 128) sW[i] = Wv[i];
    if (threadIdx.x < 64)
        sb[threadIdx.x] = (which == 2) ? bsrc[threadIdx.x] : 0.0f;
    __syncthreads();

    const int n = blockIdx.x * 128 + threadIdx.x;
    if (n >= N) return;

    unsigned long long acc[32];
#pragma unroll
    for (int p = 0; p < 32; ++p) acc[p] = 0ull;

    const float4* xv = (const float4*)(nf + (size_t)n * 128);
#pragma unroll 4
    for (int k4 = 0; k4 < 32; ++k4) {
        float4 xq = xv[k4];
#pragma unroll
        for (int j = 0; j < 4; ++j) {
            float xs = (j == 0) ? xq.x : (j == 1) ? xq.y : (j == 2) ? xq.z : xq.w;
            unsigned long long xx = pack2(xs, xs);
            const int k = k4 * 4 + j;
#pragma unroll
            for (int q = 0; q < 16; ++q) {
                float4 w = sW[k * 16 + q];
                acc[2 * q]     = ffma2(xx, pack2(w.x, w.y), acc[2 * q]);
                acc[2 * q + 1] = ffma2(xx, pack2(w.z, w.w), acc[2 * q + 1]);
            }
        }
    }

    float* o = out + (size_t)n * 64;
#pragma unroll
    for (int p = 0; p < 32; ++p) {
        float2 v = unpack2(acc[p]);
        o[2 * p]     = v.x + sb[2 * p];
        o[2 * p + 1] = v.y + sb[2 * p + 1];
    }
}

// ---------------------------------------------------------------------------
// Kernel 2: edge pass 1.  One thread = one edge.
//   f_fij = efeats[e] @ W_fij  (64x64, W in shared, f32x2 FMA)
//   f_out = leaky_relu(f_ni[src] + f_nj[dst] + f_fij + bias_e)
//   res_e[e] = mean_h f_out                (written to output)
//   logit[h] = <f_out[h,:], attn[h,:]>;  ex = exp(logit)  (no max-shift:
//   softmax is shift-invariant and logits are O(1) here)
//   g_ex[e,h] = ex;  atomicAdd(g_z[dst,h], ex)
// ---------------------------------------------------------------------------
__global__ __launch_bounds__(128)
void edge_main(const float* __restrict__ efeats,
               const int*   __restrict__ src,
               const int*   __restrict__ dst,
               const float* __restrict__ Wfij,
               const float* __restrict__ attn,
               const float* __restrict__ bias_e,
               float* __restrict__ out_e,
               int E)
{
    __shared__ float4 sW[64 * 16];    // 16 KB
    __shared__ float  s_attn[64];
    __shared__ float  s_bias[64];

    const float4* Wv = (const float4*)Wfij;
    for (int i = threadIdx.x; i < 1024; i += 128) sW[i] = Wv[i];
    if (threadIdx.x < 64) {
        s_attn[threadIdx.x] = attn[threadIdx.x];
        s_bias[threadIdx.x] = bias_e[threadIdx.x];
    }
    __syncthreads();

    const int e = blockIdx.x * 128 + threadIdx.x;
    if (e >= E) return;

    unsigned long long acc[32];
#pragma unroll
    for (int p = 0; p < 32; ++p) acc[p] = 0ull;

    const float4* xv = (const float4*)(efeats + (size_t)e * 64);
#pragma unroll 4
    for (int k4 = 0; k4 < 16; ++k4) {
        float4 xq = xv[k4];
#pragma unroll
        for (int j = 0; j < 4; ++j) {
            float xs = (j == 0) ? xq.x : (j == 1) ? xq.y : (j == 2) ? xq.z : xq.w;
            unsigned long long xx = pack2(xs, xs);
            const int k = k4 * 4 + j;
#pragma unroll
            for (int q = 0; q < 16; ++q) {
                float4 w = sW[k * 16 + q];
                acc[2 * q]     = ffma2(xx, pack2(w.x, w.y), acc[2 * q]);
                acc[2 * q + 1] = ffma2(xx, pack2(w.z, w.w), acc[2 * q + 1]);
            }
        }
    }

    const int s = src[e];
    const int d = dst[e];
    const float4* av = (const float4*)(g_fni + (size_t)s * 64);
    const float4* bv = (const float4*)(g_fnj + (size_t)d * 64);

    float re[16];
    float lg[4];
#pragma unroll
    for (int i = 0; i < 16; ++i) re[i] = 0.0f;
#pragma unroll
    for (int h = 0; h < 4; ++h) lg[h] = 0.0f;

#pragma unroll
    for (int q = 0; q < 16; ++q) {           // columns 4q..4q+3, head = q>>2
        float4 fa = av[q];
        float4 fb = bv[q];
        float2 v0 = unpack2(acc[2 * q]);
        float2 v1 = unpack2(acc[2 * q + 1]);
        float c0 = v0.x + fa.x + fb.x + s_bias[4 * q + 0];
        float c1 = v0.y + fa.y + fb.y + s_bias[4 * q + 1];
        float c2 = v1.x + fa.z + fb.z + s_bias[4 * q + 2];
        float c3 = v1.y + fa.w + fb.w + s_bias[4 * q + 3];
        c0 = (c0 > 0.0f) ? c0 : 0.01f * c0;
        c1 = (c1 > 0.0f) ? c1 : 0.01f * c1;
        c2 = (c2 > 0.0f) ? c2 : 0.01f * c2;
        c3 = (c3 > 0.0f) ? c3 : 0.01f * c3;
        const int h = q >> 2;
        const int dc = (q & 3) * 4;
        lg[h] += c0 * s_attn[4 * q + 0] + c1 * s_attn[4 * q + 1]
               + c2 * s_attn[4 * q + 2] + c3 * s_attn[4 * q + 3];
        re[dc + 0] += c0; re[dc + 1] += c1; re[dc + 2] += c2; re[dc + 3] += c3;
    }

    float4* ov = (float4*)(out_e + (size_t)e * 16);
#pragma unroll
    for (int t = 0; t < 4; ++t)
        ov[t] = make_float4(re[4 * t] * 0.25f, re[4 * t + 1] * 0.25f,
                            re[4 * t + 2] * 0.25f, re[4 * t + 3] * 0.25f);

    float* exo = g_ex + (size_t)e * 4;
#pragma unroll
    for (int h = 0; h < 4; ++h) {
        float ex = expf(lg[h]);
        exo[h] = ex;
        atomicAdd(&g_z[(size_t)d * 4 + h], ex);
    }
}

// ---------------------------------------------------------------------------
// Kernel 3: edge pass 2.  a = ex / z[dst];  res_n[dst] += mean_h a_h*h_src[src,h]
// ---------------------------------------------------------------------------
__global__ __launch_bounds__(256)
void edge_aggr(const int* __restrict__ src,
               const int* __restrict__ dst,
               float* __restrict__ out_n,
               int E)
{
    const int e = blockIdx.x * 256 + threadIdx.x;
    if (e >= E) return;
    const int s = src[e];
    const int d = dst[e];

    float4 ex4 = *(const float4*)(g_ex + (size_t)e * 4);
    float4 z4  = *(const float4*)(g_z  + (size_t)d * 4);
    const float a0 = ex4.x / z4.x;
    const float a1 = ex4.y / z4.y;
    const float a2 = ex4.z / z4.z;
    const float a3 = ex4.w / z4.w;

    const float4* hv = (const float4*)(g_hsrc + (size_t)s * 64);
    float* on = out_n + (size_t)d * 16;
#pragma unroll
    for (int q = 0; q < 4; ++q) {
        float4 h0 = hv[q];
        float4 h1 = hv[4 + q];
        float4 h2 = hv[8 + q];
        float4 h3 = hv[12 + q];
        float m0 = 0.25f * (a0 * h0.x + a1 * h1.x + a2 * h2.x + a3 * h3.x);
        float m1 = 0.25f * (a0 * h0.y + a1 * h1.y + a2 * h2.y + a3 * h3.y);
        float m2 = 0.25f * (a0 * h0.z + a1 * h1.z + a2 * h2.z + a3 * h3.z);
        float m3 = 0.25f * (a0 * h0.w + a1 * h1.w + a2 * h2.w + a3 * h3.w);
        atomicAdd(on + 4 * q + 0, m0);
        atomicAdd(on + 4 * q + 1, m1);
        atomicAdd(on + 4 * q + 2, m2);
        atomicAdd(on + 4 * q + 3, m3);
    }
}

// ---------------------------------------------------------------------------
extern "C" void kernel_launch(void* const* d_in, const int* in_sizes, int n_in,
                              void* d_out, int out_size)
{
    const float* nfeats = (const float*)d_in[0];
    const float* efeats = (const float*)d_in[1];
    const int*   src    = (const int*)  d_in[2];
    const int*   dst    = (const int*)  d_in[3];
    const float* Wni    = (const float*)d_in[4];
    const float* Wnj    = (const float*)d_in[5];
    const float* Wfij   = (const float*)d_in[6];
    const float* Wsrc   = (const float*)d_in[7];
    const float* bsrc   = (const float*)d_in[8];
    const float* attn   = (const float*)d_in[9];
    const float* biase  = (const float*)d_in[10];

    const int N = in_sizes[0] / 128;
    const int E = in_sizes[2];

    float* out_n = (float*)d_out;
    float* out_e = out_n + (size_t)N * 16;

    zero_kernel<<<(N * 16 + 255) / 256, 256>>>(out_n, N);

    dim3 g1((N + 127) / 128, 3);
    node_gemm<<<g1, 128>>>(nfeats, Wni, Wnj, Wsrc, bsrc, N);

    edge_main<<<(E + 127) / 128, 128>>>(efeats, src, dst, Wfij, attn, biase,
                                        out_e, E);

    edge_aggr<<<(E + 255) / 256, 256>>>(src, dst, out_n, E);
}

// round 2
// speedup vs baseline: 1.1040x; 1.1040x over previous
#include <cuda_runtime.h>
#include <cstdint>

// ---------------------------------------------------------------------------
// AggrEGATConv fused EGAT convolution.
//   output: res_n [N,16] followed by res_e [E,16], f32
// ---------------------------------------------------------------------------

#define MAXN 100000
#define MAXE 1600000

__device__ float g_fni [(size_t)MAXN * 64];
__device__ float g_fnj [(size_t)MAXN * 64];
__device__ float g_hsrc[(size_t)MAXN * 64];
__device__ float g_ex  [(size_t)MAXE * 4];
__device__ float g_z   [(size_t)MAXN * 4];

// ---- packed f32x2 helpers -------------------------------------------------
__device__ __forceinline__ unsigned long long pack2(float x, float y) {
    unsigned long long r;
    asm("mov.b64 %0, {%1, %2};"
        : "=l"(r) : "r"(__float_as_uint(x)), "r"(__float_as_uint(y)));
    return r;
}
__device__ __forceinline__ unsigned long long ffma2(unsigned long long a,
                                                    unsigned long long b,
                                                    unsigned long long c) {
    unsigned long long d;
    asm("fma.rn.f32x2 %0, %1, %2, %3;" : "=l"(d) : "l"(a), "l"(b), "l"(c));
    return d;
}
__device__ __forceinline__ float2 unpack2(unsigned long long v) {
    unsigned lo, hi;
    asm("mov.b64 {%0, %1}, %2;" : "=r"(lo), "=r"(hi) : "l"(v));
    return make_float2(__uint_as_float(lo), __uint_as_float(hi));
}
__device__ __forceinline__ void red_add_v4(float* p, float a, float b,
                                           float c, float d) {
    asm volatile("red.global.add.v4.f32 [%0], {%1, %2, %3, %4};"
                 :: "l"(p), "f"(a), "f"(b), "f"(c), "f"(d) : "memory");
}

// ---------------------------------------------------------------------------
// Kernel 0: zero res_n and z.
// ---------------------------------------------------------------------------
__global__ void zero_kernel(float* __restrict__ out_n, int N) {
    int i = blockIdx.x * 256 + threadIdx.x;
    if (i < N * 16) out_n[i] = 0.0f;
    if (i < N * 4)  g_z[i]   = 0.0f;
}

// ---------------------------------------------------------------------------
// Kernel 1: node GEMMs (W_ni, W_nj, W_src+b).  One thread = one node.
// Shared W pre-packed as f32x2 pairs: LDS.128 -> two aligned 64b operands,
// zero repack MOVs in the inner loop.
// ---------------------------------------------------------------------------
__global__ __launch_bounds__(256)
void node_gemm(const float* __restrict__ nf,
               const float* __restrict__ Wni,
               const float* __restrict__ Wnj,
               const float* __restrict__ Wsrc,
               const float* __restrict__ bsrc,
               int N)
{
    __shared__ ulonglong2 sW[128 * 16];   // 32 KB, pre-packed pairs
    __shared__ float      sb[64];

    const int which = blockIdx.y;
    const float* W = (which == 0) ? Wni : (which == 1) ? Wnj : Wsrc;
    float* out = (which == 0) ? g_fni : (which == 1) ? g_fnj : g_hsrc;

    const float4* Wv = (const float4*)W;
    for (int i = threadIdx.x; i < 2048; i += 256) {
        float4 w = Wv[i];
        ulonglong2 u;
        u.x = pack2(w.x, w.y);
        u.y = pack2(w.z, w.w);
        sW[i] = u;
    }
    if (threadIdx.x < 64)
        sb[threadIdx.x] = (which == 2) ? bsrc[threadIdx.x] : 0.0f;
    __syncthreads();

    const int n = blockIdx.x * 256 + threadIdx.x;
    if (n >= N) return;

    unsigned long long acc[32];
#pragma unroll
    for (int p = 0; p < 32; ++p) acc[p] = 0ull;

    const float4* xv = (const float4*)(nf + (size_t)n * 128);
#pragma unroll 4
    for (int k4 = 0; k4 < 32; ++k4) {
        float4 xq = xv[k4];
#pragma unroll
        for (int j = 0; j < 4; ++j) {
            float xs = (j == 0) ? xq.x : (j == 1) ? xq.y : (j == 2) ? xq.z : xq.w;
            unsigned long long xx = pack2(xs, xs);
            const int k = k4 * 4 + j;
#pragma unroll
            for (int q = 0; q < 16; ++q) {
                ulonglong2 w = sW[k * 16 + q];
                acc[2 * q]     = ffma2(xx, w.x, acc[2 * q]);
                acc[2 * q + 1] = ffma2(xx, w.y, acc[2 * q + 1]);
            }
        }
    }

    float* o = out + (size_t)n * 64;
#pragma unroll
    for (int p = 0; p < 32; ++p) {
        float2 v = unpack2(acc[p]);
        o[2 * p]     = v.x + sb[2 * p];
        o[2 * p + 1] = v.y + sb[2 * p + 1];
    }
}

// ---------------------------------------------------------------------------
// Kernel 2: edge pass 1.  One thread = one edge.
//   f_fij GEMM (packed-pair smem W) + gather f_ni/f_nj + leaky + res_e +
//   logits -> exp -> g_ex, vector red into g_z[dst].
// ---------------------------------------------------------------------------
__global__ __launch_bounds__(256)
void edge_main(const float* __restrict__ efeats,
               const int*   __restrict__ src,
               const int*   __restrict__ dst,
               const float* __restrict__ Wfij,
               const float* __restrict__ attn,
               const float* __restrict__ bias_e,
               float* __restrict__ out_e,
               int E)
{
    __shared__ ulonglong2 sW[64 * 16];    // 16 KB
    __shared__ float s_attn[64];
    __shared__ float s_bias[64];

    const float4* Wv = (const float4*)Wfij;
    for (int i = threadIdx.x; i < 1024; i += 256) {
        float4 w = Wv[i];
        ulonglong2 u;
        u.x = pack2(w.x, w.y);
        u.y = pack2(w.z, w.w);
        sW[i] = u;
    }
    if (threadIdx.x < 64) {
        s_attn[threadIdx.x] = attn[threadIdx.x];
        s_bias[threadIdx.x] = bias_e[threadIdx.x];
    }
    __syncthreads();

    const int e = blockIdx.x * 256 + threadIdx.x;
    if (e >= E) return;

    const int s = src[e];       // issue index loads early
    const int d = dst[e];

    unsigned long long acc[32];
#pragma unroll
    for (int p = 0; p < 32; ++p) acc[p] = 0ull;

    const float4* xv = (const float4*)(efeats + (size_t)e * 64);
#pragma unroll 4
    for (int k4 = 0; k4 < 16; ++k4) {
        float4 xq = xv[k4];
#pragma unroll
        for (int j = 0; j < 4; ++j) {
            float xs = (j == 0) ? xq.x : (j == 1) ? xq.y : (j == 2) ? xq.z : xq.w;
            unsigned long long xx = pack2(xs, xs);
            const int k = k4 * 4 + j;
#pragma unroll
            for (int q = 0; q < 16; ++q) {
                ulonglong2 w = sW[k * 16 + q];
                acc[2 * q]     = ffma2(xx, w.x, acc[2 * q]);
                acc[2 * q + 1] = ffma2(xx, w.y, acc[2 * q + 1]);
            }
        }
    }

    const float4* av = (const float4*)(g_fni + (size_t)s * 64);
    const float4* bv = (const float4*)(g_fnj + (size_t)d * 64);

    float re[16];
    float lg[4];
#pragma unroll
    for (int i = 0; i < 16; ++i) re[i] = 0.0f;
#pragma unroll
    for (int h = 0; h < 4; ++h) lg[h] = 0.0f;

#pragma unroll
    for (int q = 0; q < 16; ++q) {           // cols 4q..4q+3, head = q>>2
        float4 fa = av[q];
        float4 fb = bv[q];
        float2 v0 = unpack2(acc[2 * q]);
        float2 v1 = unpack2(acc[2 * q + 1]);
        float c0 = v0.x + fa.x + fb.x + s_bias[4 * q + 0];
        float c1 = v0.y + fa.y + fb.y + s_bias[4 * q + 1];
        float c2 = v1.x + fa.z + fb.z + s_bias[4 * q + 2];
        float c3 = v1.y + fa.w + fb.w + s_bias[4 * q + 3];
        c0 = (c0 > 0.0f) ? c0 : 0.01f * c0;
        c1 = (c1 > 0.0f) ? c1 : 0.01f * c1;
        c2 = (c2 > 0.0f) ? c2 : 0.01f * c2;
        c3 = (c3 > 0.0f) ? c3 : 0.01f * c3;
        const int h = q >> 2;
        const int dc = (q & 3) * 4;
        lg[h] += c0 * s_attn[4 * q + 0] + c1 * s_attn[4 * q + 1]
               + c2 * s_attn[4 * q + 2] + c3 * s_attn[4 * q + 3];
        re[dc + 0] += c0; re[dc + 1] += c1; re[dc + 2] += c2; re[dc + 3] += c3;
    }

    float4* ov = (float4*)(out_e + (size_t)e * 16);
#pragma unroll
    for (int t = 0; t < 4; ++t)
        ov[t] = make_float4(re[4 * t] * 0.25f, re[4 * t + 1] * 0.25f,
                            re[4 * t + 2] * 0.25f, re[4 * t + 3] * 0.25f);

    float e0 = expf(lg[0]);
    float e1 = expf(lg[1]);
    float e2 = expf(lg[2]);
    float e3 = expf(lg[3]);
    *(float4*)(g_ex + (size_t)e * 4) = make_float4(e0, e1, e2, e3);
    red_add_v4(&g_z[(size_t)d * 4], e0, e1, e2, e3);
}

// ---------------------------------------------------------------------------
// Kernel 3: invert z once per (node, head): z <- 1/z
// ---------------------------------------------------------------------------
__global__ void inv_z(int N) {
    int i = blockIdx.x * 256 + threadIdx.x;
    if (i < N * 4) g_z[i] = __frcp_rn(g_z[i]);
}

// ---------------------------------------------------------------------------
// Kernel 4: edge pass 2.  a = ex * zinv[dst];
//           res_n[dst] += mean_h a_h * h_src[src, h]   (vector red)
// ---------------------------------------------------------------------------
__global__ __launch_bounds__(256)
void edge_aggr(const int* __restrict__ src,
               const int* __restrict__ dst,
               float* __restrict__ out_n,
               int E)
{
    const int e = blockIdx.x * 256 + threadIdx.x;
    if (e >= E) return;
    const int s = src[e];
    const int d = dst[e];

    float4 ex4 = *(const float4*)(g_ex + (size_t)e * 4);
    float4 zi4 = *(const float4*)(g_z  + (size_t)d * 4);
    const float a0 = 0.25f * ex4.x * zi4.x;
    const float a1 = 0.25f * ex4.y * zi4.y;
    const float a2 = 0.25f * ex4.z * zi4.z;
    const float a3 = 0.25f * ex4.w * zi4.w;

    const float4* hv = (const float4*)(g_hsrc + (size_t)s * 64);
    float* on = out_n + (size_t)d * 16;
#pragma unroll
    for (int q = 0; q < 4; ++q) {
        float4 h0 = hv[q];
        float4 h1 = hv[4 + q];
        float4 h2 = hv[8 + q];
        float4 h3 = hv[12 + q];
        float m0 = a0 * h0.x + a1 * h1.x + a2 * h2.x + a3 * h3.x;
        float m1 = a0 * h0.y + a1 * h1.y + a2 * h2.y + a3 * h3.y;
        float m2 = a0 * h0.z + a1 * h1.z + a2 * h2.z + a3 * h3.z;
        float m3 = a0 * h0.w + a1 * h1.w + a2 * h2.w + a3 * h3.w;
        red_add_v4(on + 4 * q, m0, m1, m2, m3);
    }
}

// ---------------------------------------------------------------------------
extern "C" void kernel_launch(void* const* d_in, const int* in_sizes, int n_in,
                              void* d_out, int out_size)
{
    const float* nfeats = (const float*)d_in[0];
    const float* efeats = (const float*)d_in[1];
    const int*   src    = (const int*)  d_in[2];
    const int*   dst    = (const int*)  d_in[3];
    const float* Wni    = (const float*)d_in[4];
    const float* Wnj    = (const float*)d_in[5];
    const float* Wfij   = (const float*)d_in[6];
    const float* Wsrc   = (const float*)d_in[7];
    const float* bsrc   = (const float*)d_in[8];
    const float* attn   = (const float*)d_in[9];
    const float* biase  = (const float*)d_in[10];

    const int N = in_sizes[0] / 128;
    const int E = in_sizes[2];

    float* out_n = (float*)d_out;
    float* out_e = out_n + (size_t)N * 16;

    zero_kernel<<<(N * 16 + 255) / 256, 256>>>(out_n, N);

    dim3 g1((N + 255) / 256, 3);
    node_gemm<<<g1, 256>>>(nfeats, Wni, Wnj, Wsrc, bsrc, N);

    edge_main<<<(E + 255) / 256, 256>>>(efeats, src, dst, Wfij, attn, biase,
                                        out_e, E);

    inv_z<<<(N * 4 + 255) / 256, 256>>>(N);

    edge_aggr<<<(E + 255) / 256, 256>>>(src, dst, out_n, E);
}